// round 11
// baseline (speedup 1.0000x reference)
#include <cuda_runtime.h>
#include <cuda_fp16.h>
#include <cstdint>

// ---------------------------------------------------------------------------
// Problem shape (fixed by the reference)
// ---------------------------------------------------------------------------
constexpr int M = 4096;      // B*S
constexpr int N = 16384;     // out_features
constexpr int K = 4096;      // in_features

// GEMM tiling (measured-best R8 configuration)
constexpr int BM = 128;
constexpr int BN = 256;
constexpr int BK = 64;                      // halves per k-tile = 128 B/row
constexpr int KT = K / BK;                  // 64 k-iterations
constexpr int STAGES = 4;

constexpr int A_BYTES = BM * 128;           // 16 KB
constexpr int B_BYTES = BN * 128;           // 32 KB
constexpr int STAGE_BYTES = A_BYTES + B_BYTES;        // 48 KB
constexpr int SMEM_TOTAL  = STAGES * STAGE_BYTES;     // 192 KB

// Scratch operand buffers (device globals: the sanctioned no-alloc scratch)
__device__ __align__(1024) __half g_XH[(size_t)M * K];   // fp16 X,   [M][K]
__device__ __align__(1024) __half g_WH[(size_t)N * K];   // deq W^T,  [N][K]

// ---------------------------------------------------------------------------
// prep_x: X fp32 (holding exact fp16 values) -> fp16. Lossless.
// ---------------------------------------------------------------------------
__global__ void prep_x_kernel(const float4* __restrict__ X) {
    size_t i = (size_t)blockIdx.x * blockDim.x + threadIdx.x;   // < M*K/4
    float4 v = X[i];
    __half2* dst = reinterpret_cast<__half2*>(g_XH);
    dst[2 * i]     = __floats2half2_rn(v.x, v.y);
    dst[2 * i + 1] = __floats2half2_rn(v.z, v.w);
}

// ---------------------------------------------------------------------------
// prep_w: inline dtype detection (int8 vs sign-extended int32 delivery; R6
// ncu confirmed int32, int8 path kept correct) + dequantize + transpose:
//   WH[n][k] = fp16((W[k][n] + off[n]) * sc[n])
// q+off exact in fp32, product exact in fp32, single fp16 rounding ->
// bit-identical to the reference's all-fp16 dequant (passes at 5.559e-5).
// One 32(n) x 32(k) output tile per block, 256 flat threads.
// ---------------------------------------------------------------------------
__global__ void prep_w_kernel(const void* __restrict__ Wraw,
                              const float* __restrict__ sc,
                              const float* __restrict__ off) {
    __shared__ __half tile[32][36];
    __shared__ int s_w32;

    const int tid = threadIdx.x;
    if (tid == 0) {
        const unsigned char* wb = (const unsigned char*)Wraw;
        int all = 1;
        #pragma unroll
        for (int i = 0; i < 16; i++) {
            unsigned char b1 = wb[4 * i + 1], b2 = wb[4 * i + 2], b3 = wb[4 * i + 3];
            all &= (int)(((b1 == 0u) || (b1 == 0xFFu)) && (b2 == b1) && (b3 == b1));
        }
        s_w32 = all;
    }
    __syncthreads();

    const int n0 = blockIdx.x * 32, k0 = blockIdx.y * 32;

    if (s_w32) {
        // int32 delivery (hot path), fully vectorized
        const int tx = tid & 7;            // 0..7  (n/4 chunk)
        const int ty = tid >> 3;           // 0..31 (k row)
        const float4 s = ((const float4*)sc)[(n0 >> 2) + tx];
        const float4 o = ((const float4*)off)[(n0 >> 2) + tx];
        const int4 q = ((const int4*)Wraw)[((size_t)(k0 + ty) * N + n0) / 4 + tx];
        tile[ty][tx * 4 + 0] = __float2half_rn(((float)q.x + o.x) * s.x);
        tile[ty][tx * 4 + 1] = __float2half_rn(((float)q.y + o.y) * s.y);
        tile[ty][tx * 4 + 2] = __float2half_rn(((float)q.z + o.z) * s.z);
        tile[ty][tx * 4 + 3] = __float2half_rn(((float)q.w + o.w) * s.w);
        __syncthreads();
        __half h[4];
        #pragma unroll
        for (int j = 0; j < 4; j++) h[j] = tile[tx * 4 + j][ty];
        *reinterpret_cast<uint2*>(&g_WH[(size_t)(n0 + ty) * K + k0 + tx * 4]) =
            *reinterpret_cast<const uint2*>(h);
    } else {
        // int8 delivery (fallback)
        const int tx = tid & 31;           // n within tile
        const int ty = tid >> 5;           // 0..7
        const float s = sc[n0 + tx], o = off[n0 + tx];
        const int8_t* W8 = (const int8_t*)Wraw;
        #pragma unroll
        for (int j = 0; j < 4; j++) {
            const int k = k0 + ty + j * 8;
            int q = (int)W8[(size_t)k * N + n0 + tx];
            tile[ty + j * 8][tx] = __float2half_rn(((float)q + o) * s);
        }
        __syncthreads();
        #pragma unroll
        for (int j = 0; j < 4; j++) {
            const int n = n0 + ty + j * 8;
            g_WH[(size_t)n * K + k0 + tx] = tile[tx][ty + j * 8];
        }
    }
}

// ---------------------------------------------------------------------------
// MMA helpers (baseline compute_103 PTX: ldmatrix + mma.sync HMMA)
// ---------------------------------------------------------------------------
__device__ __forceinline__ void ldsm4(uint32_t* r, uint32_t addr) {
    asm volatile("ldmatrix.sync.aligned.m8n8.x4.shared.b16 {%0,%1,%2,%3}, [%4];"
                 : "=r"(r[0]), "=r"(r[1]), "=r"(r[2]), "=r"(r[3]) : "r"(addr));
}
__device__ __forceinline__ void mma16816(float* c, const uint32_t* a,
                                         const uint32_t* b) {
    asm volatile(
        "mma.sync.aligned.m16n8k16.row.col.f32.f16.f16.f32 "
        "{%0,%1,%2,%3}, {%4,%5,%6,%7}, {%8,%9}, {%0,%1,%2,%3};"
        : "+f"(c[0]), "+f"(c[1]), "+f"(c[2]), "+f"(c[3])
        : "r"(a[0]), "r"(a[1]), "r"(a[2]), "r"(a[3]), "r"(b[0]), "r"(b[1]));
}

// ---------------------------------------------------------------------------
// GEMM: Out[128 x 256 per CTA] = XH @ WH^T + bias. 4-stage cp.async pipeline,
// one barrier per k-iter, warp tile 64x64, double-buffered fragments.
// (Verbatim measured-best R8 kernel.)
// ---------------------------------------------------------------------------
__global__ __launch_bounds__(256, 1)
void gemm_kernel(const float* __restrict__ Bias, float* __restrict__ Out)
{
    extern __shared__ __align__(1024) char smem[];
    const uint32_t sb = (uint32_t)__cvta_generic_to_shared(smem);
    const int tid  = threadIdx.x, lane = tid & 31, wid = tid >> 5;
    const int wm   = wid & 1;              // 2 m-slabs of 64 rows
    const int wn   = wid >> 1;             // 4 n-slabs of 64 cols
    const int bm   = blockIdx.x * BM;      // grid.x = 32 (m fastest -> L2 reuse)
    const int bn   = blockIdx.y * BN;

    // cp.async mapping: warp covers 4 rows x 8 chunks (16B) per pass
    const int lrow   = tid >> 3;           // 0..31
    const int lchunk = tid & 7;            // 0..7
    const __half* gA = g_XH + (size_t)(bm + lrow) * K + lchunk * 8;
    const __half* gB = g_WH + (size_t)(bn + lrow) * K + lchunk * 8;
    const int lsw = lchunk ^ (lrow & 7);   // swizzled chunk

    auto issue_stage = [&](int kt) {
        const int s = kt & (STAGES - 1);
        const uint32_t As = sb + s * STAGE_BYTES;
        const uint32_t Bs = As + A_BYTES;
        const int k0 = kt * BK;
        #pragma unroll
        for (int p = 0; p < 4; p++) {
            const uint32_t dst = As + (lrow + p * 32) * 128 + (lsw << 4);
            asm volatile("cp.async.cg.shared.global [%0], [%1], 16;"
                         :: "r"(dst), "l"(gA + (size_t)p * 32 * K + k0) : "memory");
        }
        #pragma unroll
        for (int p = 0; p < 8; p++) {
            const uint32_t dst = Bs + (lrow + p * 32) * 128 + (lsw << 4);
            asm volatile("cp.async.cg.shared.global [%0], [%1], 16;"
                         :: "r"(dst), "l"(gB + (size_t)p * 32 * K + k0) : "memory");
        }
        asm volatile("cp.async.commit_group;" ::: "memory");
    };

    // ldmatrix per-lane addressing constants
    const int g    = lane >> 3, lr7 = lane & 7;
    const int arow = wm * 64 + (g & 1) * 8 + lr7;   // + i*16
    const int acs  = g >> 1;                        // A k-chunk selector (0/1)
    const int brow = wn * 64 + (g >> 1) * 8 + lr7;  // + j*16
    const int bcs  = g & 1;                         // B k-chunk selector (0/1)
    const int arow7 = arow & 7, brow7 = brow & 7;

    float acc[4][8][4];
    #pragma unroll
    for (int i = 0; i < 4; i++)
        #pragma unroll
        for (int j = 0; j < 8; j++)
            #pragma unroll
            for (int c = 0; c < 4; c++)
                acc[i][j][c] = 0.0f;

    #pragma unroll
    for (int s = 0; s < STAGES - 1; s++) issue_stage(s);

    uint32_t af[2][4][4], bf[2][4][4];

    for (int kt = 0; kt < KT; kt++) {
        asm volatile("cp.async.wait_group %0;" :: "n"(STAGES - 2));
        __syncthreads();
        if (kt + STAGES - 1 < KT) issue_stage(kt + STAGES - 1);

        const int s = kt & (STAGES - 1);
        const uint32_t As = sb + s * STAGE_BYTES;
        const uint32_t Bs = As + A_BYTES;

        // Prefetch kk=0 fragments
        #pragma unroll
        for (int i = 0; i < 4; i++)
            ldsm4(af[0][i], As + (arow + i * 16) * 128 + ((acs ^ arow7) << 4));
        #pragma unroll
        for (int j = 0; j < 4; j++)
            ldsm4(bf[0][j], Bs + (brow + j * 16) * 128 + ((bcs ^ brow7) << 4));

        #pragma unroll
        for (int kk = 0; kk < 4; kk++) {
            const int cur = kk & 1, nxt = cur ^ 1;
            if (kk < 3) {
                const int ck = (kk + 1) * 2;
                #pragma unroll
                for (int i = 0; i < 4; i++)
                    ldsm4(af[nxt][i], As + (arow + i * 16) * 128 +
                                      (((ck + acs) ^ arow7) << 4));
                #pragma unroll
                for (int j = 0; j < 4; j++)
                    ldsm4(bf[nxt][j], Bs + (brow + j * 16) * 128 +
                                      (((ck + bcs) ^ brow7) << 4));
            }
            #pragma unroll
            for (int i = 0; i < 4; i++)
                #pragma unroll
                for (int jj = 0; jj < 8; jj++)
                    mma16816(acc[i][jj], af[cur][i], &bf[cur][jj >> 1][(jj & 1) * 2]);
        }
    }

    // Epilogue. Reference numerics: y = fp32( fp16(acc) + fp16(bias) ).
    const int r0  = lane >> 2;
    const int cof = (lane & 3) * 2;
    #pragma unroll
    for (int i = 0; i < 4; i++) {
        const int mrow = bm + wm * 64 + i * 16 + r0;
        #pragma unroll
        for (int jj = 0; jj < 8; jj++) {
            const int col = bn + wn * 64 + jj * 8 + cof;
            const __half b0 = __float2half_rn(__ldg(Bias + col));
            const __half b1 = __float2half_rn(__ldg(Bias + col + 1));
            float2 v0, v1;
            v0.x = __half2float(__hadd(__float2half_rn(acc[i][jj][0]), b0));
            v0.y = __half2float(__hadd(__float2half_rn(acc[i][jj][1]), b1));
            v1.x = __half2float(__hadd(__float2half_rn(acc[i][jj][2]), b0));
            v1.y = __half2float(__hadd(__float2half_rn(acc[i][jj][3]), b1));
            *reinterpret_cast<float2*>(Out + (size_t)mrow * N + col)       = v0;
            *reinterpret_cast<float2*>(Out + (size_t)(mrow + 8) * N + col) = v1;
        }
    }
}

// ---------------------------------------------------------------------------
// Host — exactly 3 launches (also puts the GEMM at ncu's -s 5 capture slot)
// ---------------------------------------------------------------------------
extern "C" void kernel_launch(void* const* d_in, const int* in_sizes, int n_in,
                              void* d_out, int out_size)
{
    // metadata order: x, weight, weight_scale, weight_offset, bias
    const float* X    = (const float*)d_in[0];
    const void*  W    = d_in[1];
    const float* Wsc  = (const float*)d_in[2];
    const float* Woff = (const float*)d_in[3];
    const float* Bias = (const float*)d_in[4];
    float*       Out  = (float*)d_out;

    prep_x_kernel<<<(int)((size_t)M * K / 4 / 256), 256>>>((const float4*)X);
    prep_w_kernel<<<dim3(N / 32, K / 32), 256>>>(W, Wsc, Woff);

    cudaFuncSetAttribute(gemm_kernel,
                         cudaFuncAttributeMaxDynamicSharedMemorySize, SMEM_TOTAL);
    gemm_kernel<<<dim3(M / BM, N / BN), 256, SMEM_TOTAL>>>(Bias, Out);
}

// round 12
// speedup vs baseline: 1.0223x; 1.0223x over previous
#include <cuda_runtime.h>
#include <cuda_fp16.h>
#include <cstdint>

// ---------------------------------------------------------------------------
// Problem shape (fixed by the reference)
// ---------------------------------------------------------------------------
constexpr int M = 4096;      // B*S
constexpr int N = 16384;     // out_features
constexpr int K = 4096;      // in_features

// GEMM tiling (measured-best R8 configuration; 2048 CTAs = 13.8 waves)
constexpr int BM = 128;
constexpr int BN = 256;
constexpr int BK = 64;                      // k per tile
constexpr int KT = K / BK;                  // 64 k-iterations
constexpr int STAGES = 4;

constexpr int A_BYTES = BM * 128;           // 16 KB ([m][k] rows of 128B)
constexpr int B_BYTES = BK * BN * 2;        // 32 KB ([k][n] rows of 512B)
constexpr int STAGE_BYTES = A_BYTES + B_BYTES;        // 48 KB
constexpr int SMEM_TOTAL  = STAGES * STAGE_BYTES;     // 192 KB

// Scratch operand buffers (device globals: the sanctioned no-alloc scratch)
__device__ __align__(1024) __half g_XH[(size_t)M * K];   // fp16 X,  [M][K]
__device__ __align__(1024) __half g_WH[(size_t)K * N];   // deq W,   [K][N] (!)

// ---------------------------------------------------------------------------
// prep_x: X fp32 (holding exact fp16 values) -> fp16. Lossless.
// ---------------------------------------------------------------------------
__global__ void prep_x_kernel(const float4* __restrict__ X) {
    size_t i = (size_t)blockIdx.x * blockDim.x + threadIdx.x;   // < M*K/4
    float4 v = X[i];
    __half2* dst = reinterpret_cast<__half2*>(g_XH);
    dst[2 * i]     = __floats2half2_rn(v.x, v.y);
    dst[2 * i + 1] = __floats2half2_rn(v.z, v.w);
}

// ---------------------------------------------------------------------------
// prep_w: pure streaming dequant, NO transpose (GEMM consumes [K][N] via
// ldmatrix.trans). Inline dtype detect (int8 vs sign-extended int32; R6 ncu
// confirmed int32 delivery, int8 path kept correct).
//   WH[k][n] = fp16((W[k][n] + off[n]) * sc[n])
// q+off exact in fp32, product exact in fp32, single fp16 rounding ->
// bit-identical to the reference's all-fp16 dequant (passes at 5.559e-5).
// ---------------------------------------------------------------------------
__global__ void prep_w_kernel(const void* __restrict__ Wraw,
                              const float4* __restrict__ sc4,
                              const float4* __restrict__ off4) {
    __shared__ int s_w32;
    if (threadIdx.x == 0) {
        const unsigned char* wb = (const unsigned char*)Wraw;
        int all = 1;
        #pragma unroll
        for (int i = 0; i < 16; i++) {
            unsigned char b1 = wb[4 * i + 1], b2 = wb[4 * i + 2], b3 = wb[4 * i + 3];
            all &= (int)(((b1 == 0u) || (b1 == 0xFFu)) && (b2 == b1) && (b3 == b1));
        }
        s_w32 = all;
    }
    __syncthreads();

    const size_t idx = (size_t)blockIdx.x * blockDim.x + threadIdx.x; // < K*N/4
    const int n4 = (int)(idx & (N / 4 - 1));            // N/4 = 4096 (pow2)
    const float4 s = sc4[n4];
    const float4 o = off4[n4];

    int4 q;
    if (s_w32) {
        q = ((const int4*)Wraw)[idx];
    } else {
        unsigned int w = ((const unsigned int*)Wraw)[idx];
        q.x = (int)(int8_t)(w & 0xFF);
        q.y = (int)(int8_t)((w >> 8) & 0xFF);
        q.z = (int)(int8_t)((w >> 16) & 0xFF);
        q.w = (int)(int8_t)((w >> 24) & 0xFF);
    }

    __half h[4];
    h[0] = __float2half_rn(((float)q.x + o.x) * s.x);
    h[1] = __float2half_rn(((float)q.y + o.y) * s.y);
    h[2] = __float2half_rn(((float)q.z + o.z) * s.z);
    h[3] = __float2half_rn(((float)q.w + o.w) * s.w);
    reinterpret_cast<uint2*>(g_WH)[idx] = *reinterpret_cast<const uint2*>(h);
}

// ---------------------------------------------------------------------------
// MMA helpers (baseline compute_103 PTX: ldmatrix + mma.sync HMMA)
// ---------------------------------------------------------------------------
__device__ __forceinline__ void ldsm4(uint32_t* r, uint32_t addr) {
    asm volatile("ldmatrix.sync.aligned.m8n8.x4.shared.b16 {%0,%1,%2,%3}, [%4];"
                 : "=r"(r[0]), "=r"(r[1]), "=r"(r[2]), "=r"(r[3]) : "r"(addr));
}
__device__ __forceinline__ void ldsm4t(uint32_t* r, uint32_t addr) {
    asm volatile("ldmatrix.sync.aligned.m8n8.x4.trans.shared.b16 {%0,%1,%2,%3}, [%4];"
                 : "=r"(r[0]), "=r"(r[1]), "=r"(r[2]), "=r"(r[3]) : "r"(addr));
}
__device__ __forceinline__ void mma16816(float* c, const uint32_t* a,
                                         const uint32_t* b) {
    asm volatile(
        "mma.sync.aligned.m16n8k16.row.col.f32.f16.f16.f32 "
        "{%0,%1,%2,%3}, {%4,%5,%6,%7}, {%8,%9}, {%0,%1,%2,%3};"
        : "+f"(c[0]), "+f"(c[1]), "+f"(c[2]), "+f"(c[3])
        : "r"(a[0]), "r"(a[1]), "r"(a[2]), "r"(a[3]), "r"(b[0]), "r"(b[1]));
}

// ---------------------------------------------------------------------------
// GEMM: Out[128 x 256 per CTA] = XH @ WH + bias (WH is [K][N] row-major; B
// fragments via ldmatrix.trans). 4-stage cp.async pipeline, one barrier per
// k-iter, warp tile 64x64, double-buffered fragments.
// ---------------------------------------------------------------------------
__global__ __launch_bounds__(256, 1)
void gemm_kernel(const float* __restrict__ Bias, float* __restrict__ Out)
{
    extern __shared__ __align__(1024) char smem[];
    const uint32_t sb = (uint32_t)__cvta_generic_to_shared(smem);
    const int tid  = threadIdx.x, lane = tid & 31, wid = tid >> 5;
    const int wm   = wid & 1;              // 2 m-slabs of 64 rows
    const int wn   = wid >> 1;             // 4 n-slabs of 64 cols
    const int bm   = blockIdx.x * BM;      // grid.x = 32 (m fastest -> L2 reuse)
    const int bn   = blockIdx.y * BN;

    // cp.async A mapping: [m][k] 128B rows, chunk swizzle (as R8)
    const int lrow   = tid >> 3;           // 0..31
    const int lchunk = tid & 7;            // 0..7
    const __half* gA = g_XH + (size_t)(bm + lrow) * K + lchunk * 8;
    const int lswA = lchunk ^ (lrow & 7);

    // cp.async B mapping: [k][n] 512B rows (32 chunks), swizzle ch ^ (row&7).
    // Thread covers row = wid + 8p (p=0..7), chunk = lane. row&7 == wid.
    const __half* gB = g_WH + (size_t)wid * N + bn + lane * 8;
    const uint32_t bDst0 = (uint32_t)(wid * 512 + ((lane ^ wid) << 4));

    auto issue_stage = [&](int kt) {
        const int s = kt & (STAGES - 1);
        const uint32_t As = sb + s * STAGE_BYTES;
        const uint32_t Bs = As + A_BYTES;
        const int k0 = kt * BK;
        #pragma unroll
        for (int p = 0; p < 4; p++) {
            const uint32_t dst = As + (lrow + p * 32) * 128 + (lswA << 4);
            asm volatile("cp.async.cg.shared.global [%0], [%1], 16;"
                         :: "r"(dst), "l"(gA + (size_t)p * 32 * K + k0) : "memory");
        }
        #pragma unroll
        for (int p = 0; p < 8; p++) {      // B: 64 rows of 512B
            const uint32_t dst = Bs + bDst0 + p * 8 * 512;
            asm volatile("cp.async.cg.shared.global [%0], [%1], 16;"
                         :: "r"(dst), "l"(gB + (size_t)(k0 + p * 8) * N) : "memory");
        }
        asm volatile("cp.async.commit_group;" ::: "memory");
    };

    // A-fragment ldmatrix constants (as R8)
    const int g    = lane >> 3, lr7 = lane & 7;
    const int arow = wm * 64 + (g & 1) * 8 + lr7;   // + i*16
    const int acs  = g >> 1;                        // A k-chunk selector (0/1)
    const int arow7 = arow & 7;

    // B-fragment (trans) constants: lane -> row kk*16 + (lane&15),
    // n-chunk = wn*8 + j*2 + (lane>>4), phys chunk ^= (lane&7).
    const int bl15 = lane & 15;
    const int bcb  = wn * 8 + (lane >> 4);          // + j*2

    float acc[4][8][4];
    #pragma unroll
    for (int i = 0; i < 4; i++)
        #pragma unroll
        for (int j = 0; j < 8; j++)
            #pragma unroll
            for (int c = 0; c < 4; c++)
                acc[i][j][c] = 0.0f;

    #pragma unroll
    for (int s = 0; s < STAGES - 1; s++) issue_stage(s);

    uint32_t af[2][4][4], bf[2][4][4];

    for (int kt = 0; kt < KT; kt++) {
        asm volatile("cp.async.wait_group %0;" :: "n"(STAGES - 2));
        __syncthreads();
        if (kt + STAGES - 1 < KT) issue_stage(kt + STAGES - 1);

        const int s = kt & (STAGES - 1);
        const uint32_t As = sb + s * STAGE_BYTES;
        const uint32_t Bs = As + A_BYTES;
        const uint32_t bRow = Bs + bl15 * 512;

        // Prefetch kk=0 fragments
        #pragma unroll
        for (int i = 0; i < 4; i++)
            ldsm4(af[0][i], As + (arow + i * 16) * 128 + ((acs ^ arow7) << 4));
        #pragma unroll
        for (int j = 0; j < 4; j++)
            ldsm4t(bf[0][j], bRow + (((bcb + j * 2) ^ lr7) << 4));

        #pragma unroll
        for (int kk = 0; kk < 4; kk++) {
            const int cur = kk & 1, nxt = cur ^ 1;
            if (kk < 3) {
                const int ck = (kk + 1) * 2;
                #pragma unroll
                for (int i = 0; i < 4; i++)
                    ldsm4(af[nxt][i], As + (arow + i * 16) * 128 +
                                      (((ck + acs) ^ arow7) << 4));
                #pragma unroll
                for (int j = 0; j < 4; j++)
                    ldsm4t(bf[nxt][j], bRow + (kk + 1) * 16 * 512 +
                                       (((bcb + j * 2) ^ lr7) << 4));
            }
            #pragma unroll
            for (int i = 0; i < 4; i++)
                #pragma unroll
                for (int jj = 0; jj < 8; jj++)
                    mma16816(acc[i][jj], af[cur][i], &bf[cur][jj >> 1][(jj & 1) * 2]);
        }
    }

    // Epilogue. Reference numerics: y = fp32( fp16(acc) + fp16(bias) ).
    const int r0  = lane >> 2;
    const int cof = (lane & 3) * 2;
    #pragma unroll
    for (int i = 0; i < 4; i++) {
        const int mrow = bm + wm * 64 + i * 16 + r0;
        #pragma unroll
        for (int jj = 0; jj < 8; jj++) {
            const int col = bn + wn * 64 + jj * 8 + cof;
            const __half b0 = __float2half_rn(__ldg(Bias + col));
            const __half b1 = __float2half_rn(__ldg(Bias + col + 1));
            float2 v0, v1;
            v0.x = __half2float(__hadd(__float2half_rn(acc[i][jj][0]), b0));
            v0.y = __half2float(__hadd(__float2half_rn(acc[i][jj][1]), b1));
            v1.x = __half2float(__hadd(__float2half_rn(acc[i][jj][2]), b0));
            v1.y = __half2float(__hadd(__float2half_rn(acc[i][jj][3]), b1));
            *reinterpret_cast<float2*>(Out + (size_t)mrow * N + col)       = v0;
            *reinterpret_cast<float2*>(Out + (size_t)(mrow + 8) * N + col) = v1;
        }
    }
}

// ---------------------------------------------------------------------------
// Host — 3 launches
// ---------------------------------------------------------------------------
extern "C" void kernel_launch(void* const* d_in, const int* in_sizes, int n_in,
                              void* d_out, int out_size)
{
    // metadata order: x, weight, weight_scale, weight_offset, bias
    const float* X    = (const float*)d_in[0];
    const void*  W    = d_in[1];
    const float* Wsc  = (const float*)d_in[2];
    const float* Woff = (const float*)d_in[3];
    const float* Bias = (const float*)d_in[4];
    float*       Out  = (float*)d_out;

    prep_x_kernel<<<(int)((size_t)M * K / 4 / 256), 256>>>((const float4*)X);
    prep_w_kernel<<<(int)((size_t)K * N / 4 / 256), 256>>>(
        W, (const float4*)Wsc, (const float4*)Woff);

    cudaFuncSetAttribute(gemm_kernel,
                         cudaFuncAttributeMaxDynamicSharedMemorySize, SMEM_TOTAL);
    gemm_kernel<<<dim3(M / BM, N / BN), 256, SMEM_TOTAL>>>(Bias, Out);
}

// round 14
// speedup vs baseline: 1.0343x; 1.0117x over previous
#include <cuda_runtime.h>
#include <cuda_fp16.h>
#include <cstdint>

// ---------------------------------------------------------------------------
// Problem shape (fixed by the reference)
// ---------------------------------------------------------------------------
constexpr int M = 4096;      // B*S
constexpr int N = 16384;     // out_features
constexpr int K = 4096;      // in_features

// GEMM tiling (measured-best configuration)
constexpr int BM = 128;
constexpr int BN = 256;
constexpr int BK = 64;                      // k per tile
constexpr int KT = K / BK;                  // 64 k-iterations
constexpr int STAGES = 4;

constexpr int A_BYTES = BM * 128;           // 16 KB ([m][k] rows of 128B)
constexpr int B_BYTES = BK * BN * 2;        // 32 KB ([k][n] rows of 512B)
constexpr int STAGE_BYTES = A_BYTES + B_BYTES;        // 48 KB
constexpr int SMEM_TOTAL  = STAGES * STAGE_BYTES;     // 192 KB

// Scratch operand buffers (device globals: the sanctioned no-alloc scratch)
__device__ __align__(1024) __half g_XH[(size_t)M * K];   // fp16 X,  [M][K]
__device__ __align__(1024) __half g_WH[(size_t)K * N];   // deq W,   [K][N]

// ---------------------------------------------------------------------------
// Fused prep: one kernel does both conversions.
//   blocks [0, XBLK)        : X fp32 -> fp16 (lossless; X holds fp16 values)
//   blocks [XBLK, XBLK+WBLK): W dequant, streaming, no transpose:
//       WH[k][n] = fp16((W[k][n] + off[n]) * sc[n])
//   q+off exact in fp32, product exact in fp32, single fp16 rounding ->
//   bit-identical to the reference's all-fp16 dequant (passes at 5.559e-5).
// Per-thread: 32B load / 16B store on both paths. Weight dtype detect inline
// (int8 vs sign-extended int32; R6 ncu confirmed int32, int8 kept correct).
// ---------------------------------------------------------------------------
constexpr int XBLK = (int)((size_t)M * K / 8 / 256);      //  8192 blocks
constexpr int WBLK = (int)((size_t)K * N / 8 / 256);      // 32768 blocks

__global__ void prep_kernel(const float4* __restrict__ X,
                            const void*   __restrict__ Wraw,
                            const float4* __restrict__ sc4,
                            const float4* __restrict__ off4) {
    const int b = blockIdx.x;
    if (b < XBLK) {
        // ---- X convert: 2x float4 in, 1x uint4 (8 halves) out ----
        const size_t i = ((size_t)b * 256 + threadIdx.x) * 2;   // float4 index
        const float4 v0 = X[i];
        const float4 v1 = X[i + 1];
        __align__(16) __half2 h2[4];
        h2[0] = __floats2half2_rn(v0.x, v0.y);
        h2[1] = __floats2half2_rn(v0.z, v0.w);
        h2[2] = __floats2half2_rn(v1.x, v1.y);
        h2[3] = __floats2half2_rn(v1.z, v1.w);
        reinterpret_cast<uint4*>(g_XH)[i / 2] =
            *reinterpret_cast<const uint4*>(h2);
        return;
    }

    // ---- W dequant ----
    __shared__ int s_w32;
    if (threadIdx.x == 0) {
        const unsigned char* wb = (const unsigned char*)Wraw;
        int all = 1;
        #pragma unroll
        for (int i = 0; i < 16; i++) {
            unsigned char b1 = wb[4 * i + 1], b2 = wb[4 * i + 2], b3 = wb[4 * i + 3];
            all &= (int)(((b1 == 0u) || (b1 == 0xFFu)) && (b2 == b1) && (b3 == b1));
        }
        s_w32 = all;
    }
    __syncthreads();

    // 8 elements per thread: 2 int4 (int32 path) or 1 uint2 (int8 path) in,
    // 1 uint4 (8 halves) out.
    const size_t e8 = (size_t)(b - XBLK) * 256 + threadIdx.x;  // 8-elem group
    const int n4a = (int)((e8 * 2) & (N / 4 - 1));             // even index
    const float4 sA = sc4[n4a],     oA = off4[n4a];
    const float4 sB = sc4[n4a + 1], oB = off4[n4a + 1];

    int4 qa, qb;
    if (s_w32) {
        qa = ((const int4*)Wraw)[e8 * 2];
        qb = ((const int4*)Wraw)[e8 * 2 + 1];
    } else {
        const uint2 w = ((const uint2*)Wraw)[e8];
        qa.x = (int)(int8_t)(w.x & 0xFF);
        qa.y = (int)(int8_t)((w.x >> 8) & 0xFF);
        qa.z = (int)(int8_t)((w.x >> 16) & 0xFF);
        qa.w = (int)(int8_t)((w.x >> 24) & 0xFF);
        qb.x = (int)(int8_t)(w.y & 0xFF);
        qb.y = (int)(int8_t)((w.y >> 8) & 0xFF);
        qb.z = (int)(int8_t)((w.y >> 16) & 0xFF);
        qb.w = (int)(int8_t)((w.y >> 24) & 0xFF);
    }

    __align__(16) __half h[8];
    h[0] = __float2half_rn(((float)qa.x + oA.x) * sA.x);
    h[1] = __float2half_rn(((float)qa.y + oA.y) * sA.y);
    h[2] = __float2half_rn(((float)qa.z + oA.z) * sA.z);
    h[3] = __float2half_rn(((float)qa.w + oA.w) * sA.w);
    h[4] = __float2half_rn(((float)qb.x + oB.x) * sB.x);
    h[5] = __float2half_rn(((float)qb.y + oB.y) * sB.y);
    h[6] = __float2half_rn(((float)qb.z + oB.z) * sB.z);
    h[7] = __float2half_rn(((float)qb.w + oB.w) * sB.w);
    reinterpret_cast<uint4*>(g_WH)[e8] = *reinterpret_cast<const uint4*>(h);
}

// ---------------------------------------------------------------------------
// MMA helpers (baseline compute_103 PTX: ldmatrix + mma.sync HMMA)
// ---------------------------------------------------------------------------
__device__ __forceinline__ void ldsm4(uint32_t* r, uint32_t addr) {
    asm volatile("ldmatrix.sync.aligned.m8n8.x4.shared.b16 {%0,%1,%2,%3}, [%4];"
                 : "=r"(r[0]), "=r"(r[1]), "=r"(r[2]), "=r"(r[3]) : "r"(addr));
}
__device__ __forceinline__ void ldsm4t(uint32_t* r, uint32_t addr) {
    asm volatile("ldmatrix.sync.aligned.m8n8.x4.trans.shared.b16 {%0,%1,%2,%3}, [%4];"
                 : "=r"(r[0]), "=r"(r[1]), "=r"(r[2]), "=r"(r[3]) : "r"(addr));
}
__device__ __forceinline__ void mma16816(float* c, const uint32_t* a,
                                         const uint32_t* b) {
    asm volatile(
        "mma.sync.aligned.m16n8k16.row.col.f32.f16.f16.f32 "
        "{%0,%1,%2,%3}, {%4,%5,%6,%7}, {%8,%9}, {%0,%1,%2,%3};"
        : "+f"(c[0]), "+f"(c[1]), "+f"(c[2]), "+f"(c[3])
        : "r"(a[0]), "r"(a[1]), "r"(a[2]), "r"(a[3]), "r"(b[0]), "r"(b[1]));
}

// ---------------------------------------------------------------------------
// GEMM (verbatim R12-best): Out[128 x 256 per CTA] = XH @ WH + bias.
// WH is [K][N] row-major; B fragments via ldmatrix.trans. 4-stage cp.async
// pipeline, one barrier per k-iter, warp tile 64x64, double-buffered frags.
// ---------------------------------------------------------------------------
__global__ __launch_bounds__(256, 1)
void gemm_kernel(const float* __restrict__ Bias, float* __restrict__ Out)
{
    extern __shared__ __align__(1024) char smem[];
    const uint32_t sb = (uint32_t)__cvta_generic_to_shared(smem);
    const int tid  = threadIdx.x, lane = tid & 31, wid = tid >> 5;
    const int wm   = wid & 1;              // 2 m-slabs of 64 rows
    const int wn   = wid >> 1;             // 4 n-slabs of 64 cols
    const int bm   = blockIdx.x * BM;      // grid.x = 32 (m fastest -> L2 reuse)
    const int bn   = blockIdx.y * BN;

    // cp.async A mapping: [m][k] 128B rows, chunk swizzle
    const int lrow   = tid >> 3;           // 0..31
    const int lchunk = tid & 7;            // 0..7
    const __half* gA = g_XH + (size_t)(bm + lrow) * K + lchunk * 8;
    const int lswA = lchunk ^ (lrow & 7);

    // cp.async B mapping: [k][n] 512B rows (32 chunks), swizzle ch ^ (row&7).
    const __half* gB = g_WH + (size_t)wid * N + bn + lane * 8;
    const uint32_t bDst0 = (uint32_t)(wid * 512 + ((lane ^ wid) << 4));

    auto issue_stage = [&](int kt) {
        const int s = kt & (STAGES - 1);
        const uint32_t As = sb + s * STAGE_BYTES;
        const uint32_t Bs = As + A_BYTES;
        const int k0 = kt * BK;
        #pragma unroll
        for (int p = 0; p < 4; p++) {
            const uint32_t dst = As + (lrow + p * 32) * 128 + (lswA << 4);
            asm volatile("cp.async.cg.shared.global [%0], [%1], 16;"
                         :: "r"(dst), "l"(gA + (size_t)p * 32 * K + k0) : "memory");
        }
        #pragma unroll
        for (int p = 0; p < 8; p++) {      // B: 64 rows of 512B
            const uint32_t dst = Bs + bDst0 + p * 8 * 512;
            asm volatile("cp.async.cg.shared.global [%0], [%1], 16;"
                         :: "r"(dst), "l"(gB + (size_t)(k0 + p * 8) * N) : "memory");
        }
        asm volatile("cp.async.commit_group;" ::: "memory");
    };

    // A-fragment ldmatrix constants
    const int g    = lane >> 3, lr7 = lane & 7;
    const int arow = wm * 64 + (g & 1) * 8 + lr7;   // + i*16
    const int acs  = g >> 1;                        // A k-chunk selector (0/1)
    const int arow7 = arow & 7;

    // B-fragment (trans) constants
    const int bl15 = lane & 15;
    const int bcb  = wn * 8 + (lane >> 4);          // + j*2

    float acc[4][8][4];
    #pragma unroll
    for (int i = 0; i < 4; i++)
        #pragma unroll
        for (int j = 0; j < 8; j++)
            #pragma unroll
            for (int c = 0; c < 4; c++)
                acc[i][j][c] = 0.0f;

    #pragma unroll
    for (int s = 0; s < STAGES - 1; s++) issue_stage(s);

    uint32_t af[2][4][4], bf[2][4][4];

    for (int kt = 0; kt < KT; kt++) {
        asm volatile("cp.async.wait_group %0;" :: "n"(STAGES - 2));
        __syncthreads();
        if (kt + STAGES - 1 < KT) issue_stage(kt + STAGES - 1);

        const int s = kt & (STAGES - 1);
        const uint32_t As = sb + s * STAGE_BYTES;
        const uint32_t Bs = As + A_BYTES;
        const uint32_t bRow = Bs + bl15 * 512;

        // Prefetch kk=0 fragments
        #pragma unroll
        for (int i = 0; i < 4; i++)
            ldsm4(af[0][i], As + (arow + i * 16) * 128 + ((acs ^ arow7) << 4));
        #pragma unroll
        for (int j = 0; j < 4; j++)
            ldsm4t(bf[0][j], bRow + (((bcb + j * 2) ^ lr7) << 4));

        #pragma unroll
        for (int kk = 0; kk < 4; kk++) {
            const int cur = kk & 1, nxt = cur ^ 1;
            if (kk < 3) {
                const int ck = (kk + 1) * 2;
                #pragma unroll
                for (int i = 0; i < 4; i++)
                    ldsm4(af[nxt][i], As + (arow + i * 16) * 128 +
                                      (((ck + acs) ^ arow7) << 4));
                #pragma unroll
                for (int j = 0; j < 4; j++)
                    ldsm4t(bf[nxt][j], bRow + (kk + 1) * 16 * 512 +
                                       (((bcb + j * 2) ^ lr7) << 4));
            }
            #pragma unroll
            for (int i = 0; i < 4; i++)
                #pragma unroll
                for (int jj = 0; jj < 8; jj++)
                    mma16816(acc[i][jj], af[cur][i], &bf[cur][jj >> 1][(jj & 1) * 2]);
        }
    }

    // Epilogue. Reference numerics: y = fp32( fp16(acc) + fp16(bias) ).
    const int r0  = lane >> 2;
    const int cof = (lane & 3) * 2;
    #pragma unroll
    for (int i = 0; i < 4; i++) {
        const int mrow = bm + wm * 64 + i * 16 + r0;
        #pragma unroll
        for (int jj = 0; jj < 8; jj++) {
            const int col = bn + wn * 64 + jj * 8 + cof;
            const __half b0 = __float2half_rn(__ldg(Bias + col));
            const __half b1 = __float2half_rn(__ldg(Bias + col + 1));
            float2 v0, v1;
            v0.x = __half2float(__hadd(__float2half_rn(acc[i][jj][0]), b0));
            v0.y = __half2float(__hadd(__float2half_rn(acc[i][jj][1]), b1));
            v1.x = __half2float(__hadd(__float2half_rn(acc[i][jj][2]), b0));
            v1.y = __half2float(__hadd(__float2half_rn(acc[i][jj][3]), b1));
            *reinterpret_cast<float2*>(Out + (size_t)mrow * N + col)       = v0;
            *reinterpret_cast<float2*>(Out + (size_t)(mrow + 8) * N + col) = v1;
        }
    }
}

// ---------------------------------------------------------------------------
// Host — 2 launches
// ---------------------------------------------------------------------------
extern "C" void kernel_launch(void* const* d_in, const int* in_sizes, int n_in,
                              void* d_out, int out_size)
{
    // metadata order: x, weight, weight_scale, weight_offset, bias
    const float* X    = (const float*)d_in[0];
    const void*  W    = d_in[1];
    const float* Wsc  = (const float*)d_in[2];
    const float* Woff = (const float*)d_in[3];
    const float* Bias = (const float*)d_in[4];
    float*       Out  = (float*)d_out;

    prep_kernel<<<XBLK + WBLK, 256>>>((const float4*)X, W,
                                      (const float4*)Wsc, (const float4*)Woff);

    cudaFuncSetAttribute(gemm_kernel,
                         cudaFuncAttributeMaxDynamicSharedMemorySize, SMEM_TOTAL);
    gemm_kernel<<<dim3(M / BM, N / BN), 256, SMEM_TOTAL>>>(Bias, Out);
}

// round 15
// speedup vs baseline: 1.1443x; 1.1064x over previous
#include <cuda_runtime.h>
#include <cuda_fp16.h>
#include <cstdint>

// ---------------------------------------------------------------------------
// Problem shape (fixed by the reference)
// ---------------------------------------------------------------------------
constexpr int M = 4096;      // B*S
constexpr int N = 16384;     // out_features
constexpr int K = 4096;      // in_features

// GEMM tiling: 128x128 CTA tile, 3 stages, 2 CTAs/SM (96 KB smem, <=128 regs)
constexpr int BM = 128;
constexpr int BN = 128;
constexpr int BK = 64;                      // k per tile
constexpr int KT = K / BK;                  // 64 k-iterations
constexpr int STAGES = 3;

constexpr int A_BYTES = BM * 128;           // 16 KB ([m][k] rows of 128B)
constexpr int B_BYTES = BK * BN * 2;        // 16 KB ([k][n] rows of 256B)
constexpr int STAGE_BYTES = A_BYTES + B_BYTES;        // 32 KB
constexpr int SMEM_TOTAL  = STAGES * STAGE_BYTES;     // 96 KB

// Scratch operand buffers (device globals: the sanctioned no-alloc scratch)
__device__ __align__(1024) __half g_XH[(size_t)M * K];   // fp16 X,  [M][K]
__device__ __align__(1024) __half g_WH[(size_t)K * N];   // deq W,   [K][N]

// ---------------------------------------------------------------------------
// Fused prep (verbatim R14-passing): X convert + W streaming dequant.
//   WH[k][n] = fp16((W[k][n] + off[n]) * sc[n]); bit-identical numerics.
// ---------------------------------------------------------------------------
constexpr int XBLK = (int)((size_t)M * K / 8 / 256);      //  8192 blocks
constexpr int WBLK = (int)((size_t)K * N / 8 / 256);      // 32768 blocks

__global__ void prep_kernel(const float4* __restrict__ X,
                            const void*   __restrict__ Wraw,
                            const float4* __restrict__ sc4,
                            const float4* __restrict__ off4) {
    const int b = blockIdx.x;
    if (b < XBLK) {
        const size_t i = ((size_t)b * 256 + threadIdx.x) * 2;   // float4 index
        const float4 v0 = X[i];
        const float4 v1 = X[i + 1];
        __align__(16) __half2 h2[4];
        h2[0] = __floats2half2_rn(v0.x, v0.y);
        h2[1] = __floats2half2_rn(v0.z, v0.w);
        h2[2] = __floats2half2_rn(v1.x, v1.y);
        h2[3] = __floats2half2_rn(v1.z, v1.w);
        reinterpret_cast<uint4*>(g_XH)[i / 2] =
            *reinterpret_cast<const uint4*>(h2);
        return;
    }

    __shared__ int s_w32;
    if (threadIdx.x == 0) {
        const unsigned char* wb = (const unsigned char*)Wraw;
        int all = 1;
        #pragma unroll
        for (int i = 0; i < 16; i++) {
            unsigned char b1 = wb[4 * i + 1], b2 = wb[4 * i + 2], b3 = wb[4 * i + 3];
            all &= (int)(((b1 == 0u) || (b1 == 0xFFu)) && (b2 == b1) && (b3 == b1));
        }
        s_w32 = all;
    }
    __syncthreads();

    const size_t e8 = (size_t)(b - XBLK) * 256 + threadIdx.x;  // 8-elem group
    const int n4a = (int)((e8 * 2) & (N / 4 - 1));
    const float4 sA = sc4[n4a],     oA = off4[n4a];
    const float4 sB = sc4[n4a + 1], oB = off4[n4a + 1];

    int4 qa, qb;
    if (s_w32) {
        qa = ((const int4*)Wraw)[e8 * 2];
        qb = ((const int4*)Wraw)[e8 * 2 + 1];
    } else {
        const uint2 w = ((const uint2*)Wraw)[e8];
        qa.x = (int)(int8_t)(w.x & 0xFF);
        qa.y = (int)(int8_t)((w.x >> 8) & 0xFF);
        qa.z = (int)(int8_t)((w.x >> 16) & 0xFF);
        qa.w = (int)(int8_t)((w.x >> 24) & 0xFF);
        qb.x = (int)(int8_t)(w.y & 0xFF);
        qb.y = (int)(int8_t)((w.y >> 8) & 0xFF);
        qb.z = (int)(int8_t)((w.y >> 16) & 0xFF);
        qb.w = (int)(int8_t)((w.y >> 24) & 0xFF);
    }

    __align__(16) __half h[8];
    h[0] = __float2half_rn(((float)qa.x + oA.x) * sA.x);
    h[1] = __float2half_rn(((float)qa.y + oA.y) * sA.y);
    h[2] = __float2half_rn(((float)qa.z + oA.z) * sA.z);
    h[3] = __float2half_rn(((float)qa.w + oA.w) * sA.w);
    h[4] = __float2half_rn(((float)qb.x + oB.x) * sB.x);
    h[5] = __float2half_rn(((float)qb.y + oB.y) * sB.y);
    h[6] = __float2half_rn(((float)qb.z + oB.z) * sB.z);
    h[7] = __float2half_rn(((float)qb.w + oB.w) * sB.w);
    reinterpret_cast<uint4*>(g_WH)[e8] = *reinterpret_cast<const uint4*>(h);
}

// ---------------------------------------------------------------------------
// MMA helpers (baseline compute_103 PTX: ldmatrix + mma.sync HMMA)
// ---------------------------------------------------------------------------
__device__ __forceinline__ void ldsm4(uint32_t* r, uint32_t addr) {
    asm volatile("ldmatrix.sync.aligned.m8n8.x4.shared.b16 {%0,%1,%2,%3}, [%4];"
                 : "=r"(r[0]), "=r"(r[1]), "=r"(r[2]), "=r"(r[3]) : "r"(addr));
}
__device__ __forceinline__ void ldsm4t(uint32_t* r, uint32_t addr) {
    asm volatile("ldmatrix.sync.aligned.m8n8.x4.trans.shared.b16 {%0,%1,%2,%3}, [%4];"
                 : "=r"(r[0]), "=r"(r[1]), "=r"(r[2]), "=r"(r[3]) : "r"(addr));
}
__device__ __forceinline__ void mma16816(float* c, const uint32_t* a,
                                         const uint32_t* b) {
    asm volatile(
        "mma.sync.aligned.m16n8k16.row.col.f32.f16.f16.f32 "
        "{%0,%1,%2,%3}, {%4,%5,%6,%7}, {%8,%9}, {%0,%1,%2,%3};"
        : "+f"(c[0]), "+f"(c[1]), "+f"(c[2]), "+f"(c[3])
        : "r"(a[0]), "r"(a[1]), "r"(a[2]), "r"(a[3]), "r"(b[0]), "r"(b[1]));
}

// ---------------------------------------------------------------------------
// GEMM: Out[128 x 128 per CTA] = XH @ WH + bias, 2 CTAs/SM.
// WH is [K][N] row-major ([k][n] smem rows of 256B; ldmatrix.trans).
// 3-stage cp.async pipeline, one barrier per k-iter, warp tile 64x32.
// ---------------------------------------------------------------------------
__global__ __launch_bounds__(256, 2)
void gemm_kernel(const float* __restrict__ Bias, float* __restrict__ Out)
{
    extern __shared__ __align__(1024) char smem[];
    const uint32_t sb = (uint32_t)__cvta_generic_to_shared(smem);
    const int tid  = threadIdx.x, lane = tid & 31, wid = tid >> 5;
    const int wm   = wid & 1;              // 2 m-slabs of 64 rows
    const int wn   = wid >> 1;             // 4 n-slabs of 32 cols
    const int bm   = blockIdx.x * BM;      // grid.x = 32 (m fastest -> L2 reuse)
    const int bn   = blockIdx.y * BN;

    // cp.async A mapping: [m][k] 128B rows (8 chunks), 4 passes
    const int lrow   = tid >> 3;           // 0..31
    const int lchunk = tid & 7;            // 0..7
    const __half* gA = g_XH + (size_t)(bm + lrow) * K + lchunk * 8;
    const int lswA = lchunk ^ (lrow & 7);

    // cp.async B mapping: [k][n] 256B rows (16 chunks), 4 passes of 16 rows.
    const int brow0 = tid >> 4;            // 0..15  (row & 7 invariant mod 16)
    const int bch   = tid & 15;            // 0..15
    const __half* gB = g_WH + (size_t)brow0 * N + bn + bch * 8;
    const uint32_t bDst0 = (uint32_t)(brow0 * 256 + ((bch ^ (brow0 & 7)) << 4));

    auto issue_stage = [&](int kt, int s) {
        const uint32_t As = sb + s * STAGE_BYTES;
        const uint32_t Bs = As + A_BYTES;
        const int k0 = kt * BK;
        #pragma unroll
        for (int p = 0; p < 4; p++) {
            const uint32_t dst = As + (lrow + p * 32) * 128 + (lswA << 4);
            asm volatile("cp.async.cg.shared.global [%0], [%1], 16;"
                         :: "r"(dst), "l"(gA + (size_t)p * 32 * K + k0) : "memory");
        }
        #pragma unroll
        for (int p = 0; p < 4; p++) {      // B: 64 rows of 256B
            const uint32_t dst = Bs + bDst0 + p * 16 * 256;
            asm volatile("cp.async.cg.shared.global [%0], [%1], 16;"
                         :: "r"(dst), "l"(gB + (size_t)(k0 + p * 16) * N) : "memory");
        }
        asm volatile("cp.async.commit_group;" ::: "memory");
    };

    // A-fragment ldmatrix constants
    const int g    = lane >> 3, lr7 = lane & 7;
    const int arow = wm * 64 + (g & 1) * 8 + lr7;   // + i*16
    const int acs  = g >> 1;                        // A k-chunk selector (0/1)
    const int arow7 = arow & 7;

    // B-fragment (trans) constants: row = kk*16 + (lane&15),
    // n-chunk = wn*4 + j*2 + (lane>>4), phys chunk ^= lr7 (row&7 == lane&7).
    const int bl15 = lane & 15;
    const int bcb  = wn * 4 + (lane >> 4);          // + j*2

    float acc[4][4][4];
    #pragma unroll
    for (int i = 0; i < 4; i++)
        #pragma unroll
        for (int j = 0; j < 4; j++)
            #pragma unroll
            for (int c = 0; c < 4; c++)
                acc[i][j][c] = 0.0f;

    issue_stage(0, 0);
    issue_stage(1, 1);

    for (int kt = 0; kt < KT; kt++) {
        asm volatile("cp.async.wait_group %0;" :: "n"(STAGES - 2));
        __syncthreads();
        const int s = kt % STAGES;
        if (kt + STAGES - 1 < KT)
            issue_stage(kt + STAGES - 1, (kt + STAGES - 1) % STAGES);

        const uint32_t As = sb + s * STAGE_BYTES;
        const uint32_t Bs = As + A_BYTES;
        const uint32_t bRow = Bs + bl15 * 256;

        #pragma unroll
        for (int kk = 0; kk < 4; kk++) {          // 4 x k16 per k-tile
            const int ck = kk * 2;
            uint32_t af[4][4], bf[2][4];
            #pragma unroll
            for (int i = 0; i < 4; i++)
                ldsm4(af[i], As + (arow + i * 16) * 128 +
                             (((ck + acs) ^ arow7) << 4));
            #pragma unroll
            for (int j = 0; j < 2; j++)
                ldsm4t(bf[j], bRow + kk * 16 * 256 +
                              (((bcb + j * 2) ^ lr7) << 4));
            #pragma unroll
            for (int i = 0; i < 4; i++)
                #pragma unroll
                for (int jj = 0; jj < 4; jj++)
                    mma16816(acc[i][jj], af[i], &bf[jj >> 1][(jj & 1) * 2]);
        }
    }

    // Epilogue. Reference numerics: y = fp32( fp16(acc) + fp16(bias) ).
    const int r0  = lane >> 2;
    const int cof = (lane & 3) * 2;
    #pragma unroll
    for (int i = 0; i < 4; i++) {
        const int mrow = bm + wm * 64 + i * 16 + r0;
        #pragma unroll
        for (int jj = 0; jj < 4; jj++) {
            const int col = bn + wn * 32 + jj * 8 + cof;
            const __half b0 = __float2half_rn(__ldg(Bias + col));
            const __half b1 = __float2half_rn(__ldg(Bias + col + 1));
            float2 v0, v1;
            v0.x = __half2float(__hadd(__float2half_rn(acc[i][jj][0]), b0));
            v0.y = __half2float(__hadd(__float2half_rn(acc[i][jj][1]), b1));
            v1.x = __half2float(__hadd(__float2half_rn(acc[i][jj][2]), b0));
            v1.y = __half2float(__hadd(__float2half_rn(acc[i][jj][3]), b1));
            *reinterpret_cast<float2*>(Out + (size_t)mrow * N + col)       = v0;
            *reinterpret_cast<float2*>(Out + (size_t)(mrow + 8) * N + col) = v1;
        }
    }
}

// ---------------------------------------------------------------------------
// Host — 2 launches
// ---------------------------------------------------------------------------
extern "C" void kernel_launch(void* const* d_in, const int* in_sizes, int n_in,
                              void* d_out, int out_size)
{
    // metadata order: x, weight, weight_scale, weight_offset, bias
    const float* X    = (const float*)d_in[0];
    const void*  W    = d_in[1];
    const float* Wsc  = (const float*)d_in[2];
    const float* Woff = (const float*)d_in[3];
    const float* Bias = (const float*)d_in[4];
    float*       Out  = (float*)d_out;

    prep_kernel<<<XBLK + WBLK, 256>>>((const float4*)X, W,
                                      (const float4*)Wsc, (const float4*)Woff);

    cudaFuncSetAttribute(gemm_kernel,
                         cudaFuncAttributeMaxDynamicSharedMemorySize, SMEM_TOTAL);
    gemm_kernel<<<dim3(M / BM, N / BN), 256, SMEM_TOTAL>>>(Bias, Out);
}